// round 4
// baseline (speedup 1.0000x reference)
#include <cuda_runtime.h>
#include <cuda_bf16.h>

#define NBLOCKS (148 * 16)   // 2368: exact multiple of SM count
#define NTHREADS 256

__device__ float g_partials[NBLOCKS];
__device__ int   g_ticket = 0;   // reset to 0 by the last block each call

__device__ __forceinline__ float sample_loss(float l0, float l1, float l2,
                                             float t0, float t1, float t2,
                                             int h, float conf) {
    // adaptive temperature (branch-free select)
    float low = fminf(3.7f - 2.0f * conf, 3.0f);
    float T   = (conf > 0.9f) ? 1.5f : ((conf > 0.6f) ? 2.0f : low);
    float invT = 1.0f / T;

    // KL(t || softmax(l/T)) = lse(l/T) + sum t*(log t - l/T)   (sum t = 1)
    float s0 = l0 * invT, s1 = l1 * invT, s2 = l2 * invT;
    float m  = fmaxf(s0, fmaxf(s1, s2));
    float lse = m + __logf(__expf(s0 - m) + __expf(s1 - m) + __expf(s2 - m));
    float kl = lse;
    kl += (t0 > 0.0f) ? t0 * (__logf(t0) - s0) : 0.0f;
    kl += (t1 > 0.0f) ? t1 * (__logf(t1) - s1) : 0.0f;
    kl += (t2 > 0.0f) ? t2 * (__logf(t2) - s2) : 0.0f;

    // CE = lse(l) - l[hard]
    float m2   = fmaxf(l0, fmaxf(l1, l2));
    float lse2 = m2 + __logf(__expf(l0 - m2) + __expf(l1 - m2) + __expf(l2 - m2));
    float lh   = (h == 0) ? l0 : ((h == 1) ? l1 : l2);
    float ce   = lse2 - lh;

    return 0.5f * (kl + ce);   // ALPHA = 0.5
}

__global__ void __launch_bounds__(NTHREADS)
adl_fused_kernel(const float4* __restrict__ logits4,
                 const int4*   __restrict__ hard4,
                 const float4* __restrict__ soft4,
                 const float4* __restrict__ conf4,
                 int ngroups /* = B/4 */,
                 float* __restrict__ out,
                 float inv_n) {
    float acc = 0.0f;
    const int stride = gridDim.x * blockDim.x;
    for (int g = blockIdx.x * blockDim.x + threadIdx.x; g < ngroups; g += stride) {
        const float4 L0 = logits4[3 * g + 0];
        const float4 L1 = logits4[3 * g + 1];
        const float4 L2 = logits4[3 * g + 2];
        const float4 S0 = soft4[3 * g + 0];
        const float4 S1 = soft4[3 * g + 1];
        const float4 S2 = soft4[3 * g + 2];
        const int4   H  = hard4[g];
        const float4 Cf = conf4[g];

        acc += sample_loss(L0.x, L0.y, L0.z, S0.x, S0.y, S0.z, H.x, Cf.x);
        acc += sample_loss(L0.w, L1.x, L1.y, S0.w, S1.x, S1.y, H.y, Cf.y);
        acc += sample_loss(L1.z, L1.w, L2.x, S1.z, S1.w, S2.x, H.z, Cf.z);
        acc += sample_loss(L2.y, L2.z, L2.w, S2.y, S2.z, S2.w, H.w, Cf.w);
    }

    // block reduction: warp shuffle then shared
    __shared__ float warp_sums[NTHREADS / 32];
    #pragma unroll
    for (int off = 16; off > 0; off >>= 1)
        acc += __shfl_down_sync(0xFFFFFFFFu, acc, off);
    if ((threadIdx.x & 31) == 0)
        warp_sums[threadIdx.x >> 5] = acc;
    __syncthreads();

    __shared__ bool is_last;
    if (threadIdx.x == 0) {
        float v = 0.0f;
        #pragma unroll
        for (int w = 0; w < NTHREADS / 32; w++) v += warp_sums[w];
        g_partials[blockIdx.x] = v;
        __threadfence();
        int t = atomicAdd(&g_ticket, 1);
        is_last = (t == NBLOCKS - 1);
    }
    __syncthreads();

    if (is_last) {
        // Final reduction over the 2368 partials (L2-hot), fixed order -> deterministic.
        __shared__ double dwarp[NTHREADS / 32];
        const volatile float* vp = g_partials;
        double dacc = 0.0;
        for (int i = threadIdx.x; i < NBLOCKS; i += NTHREADS)
            dacc += (double)vp[i];
        #pragma unroll
        for (int off = 16; off > 0; off >>= 1)
            dacc += __shfl_down_sync(0xFFFFFFFFu, dacc, off);
        if ((threadIdx.x & 31) == 0)
            dwarp[threadIdx.x >> 5] = dacc;
        __syncthreads();
        if (threadIdx.x == 0) {
            double s = 0.0;
            #pragma unroll
            for (int w = 0; w < NTHREADS / 32; w++) s += dwarp[w];
            out[0] = (float)(s * (double)inv_n);
            g_ticket = 0;   // reset for next graph replay
        }
    }
}

extern "C" void kernel_launch(void* const* d_in, const int* in_sizes, int n_in,
                              void* d_out, int out_size) {
    // metadata order: logits (B*3 f32), hard_labels (B i32), soft_labels (B*3 f32), confidences (B f32)
    const float4* logits4 = (const float4*)d_in[0];
    const int4*   hard4   = (const int4*)d_in[1];
    const float4* soft4   = (const float4*)d_in[2];
    const float4* conf4   = (const float4*)d_in[3];
    const int n = in_sizes[1];          // B
    const int ngroups = n / 4;

    adl_fused_kernel<<<NBLOCKS, NTHREADS>>>(logits4, hard4, soft4, conf4,
                                            ngroups, (float*)d_out,
                                            1.0f / (float)n);
}